// round 2
// baseline (speedup 1.0000x reference)
#include <cuda_runtime.h>
#include <cuda_bf16.h>
#include <cstdint>

#define N_NODES 50000
#define N_EDGES 800000
#define HID 64
#define IN_FEATS 256
#define CAT_DIM 256

__device__ float g_cnt_out[N_NODES];
__device__ float g_cnt_in[N_NODES];
__device__ float g_dout_is[N_NODES];
__device__ float g_din_is[N_NODES];
__device__ float g_y[(size_t)N_NODES * HID];
__device__ float g_agg[(size_t)N_NODES * HID];
__device__ float g_cat[(size_t)N_NODES * CAT_DIM];
__device__ float g_agg256[(size_t)N_NODES * CAT_DIM];

__device__ __forceinline__ void red_add_v4(float* p, float4 v) {
    asm volatile("red.global.add.v4.f32 [%0], {%1, %2, %3, %4};"
                 :: "l"(p), "f"(v.x), "f"(v.y), "f"(v.z), "f"(v.w)
                 : "memory");
}

__global__ void k_zero_deg() {
    int i = blockIdx.x * blockDim.x + threadIdx.x;
    if (i < N_NODES) { g_cnt_out[i] = 0.f; g_cnt_in[i] = 0.f; }
}

__global__ void k_zero_agg64() {
    int i = blockIdx.x * blockDim.x + threadIdx.x;
    if (i < N_NODES * (HID / 4)) ((float4*)g_agg)[i] = make_float4(0.f, 0.f, 0.f, 0.f);
}

__global__ void k_zero_agg256() {
    int i = blockIdx.x * blockDim.x + threadIdx.x;
    if (i < N_NODES * (CAT_DIM / 4)) ((float4*)g_agg256)[i] = make_float4(0.f, 0.f, 0.f, 0.f);
}

__global__ void k_deg_count(const int* __restrict__ src, const int* __restrict__ dst) {
    int e = blockIdx.x * blockDim.x + threadIdx.x;
    if (e < N_EDGES) {
        atomicAdd(&g_cnt_out[src[e]], 1.f);
        atomicAdd(&g_cnt_in[dst[e]], 1.f);
    }
}

__global__ void k_deg_fin() {
    int i = blockIdx.x * blockDim.x + threadIdx.x;
    if (i < N_NODES) {
        g_dout_is[i] = rsqrtf(fmaxf(g_cnt_out[i], 1.f));
        g_din_is[i]  = rsqrtf(fmaxf(g_cnt_in[i], 1.f));
    }
}

template<int K, bool SCALE, bool BIAS>
__global__ __launch_bounds__(256)
void k_gemm64(const float* __restrict__ X, int ldx,
              const float* __restrict__ W,
              const float* __restrict__ bias,
              float* __restrict__ Y, int n)
{
    __shared__ float Xs[64][68];
    __shared__ float Ws[64][64];

    const int tid  = threadIdx.x;
    const int row0 = blockIdx.x * 64;
    const int r0   = (tid >> 4) << 2;
    const int c0   = (tid & 15) << 2;

    float acc[4][4];
    #pragma unroll
    for (int i = 0; i < 4; ++i)
        #pragma unroll
        for (int j = 0; j < 4; ++j) acc[i][j] = 0.f;

    for (int kk = 0; kk < K; kk += 64) {
        #pragma unroll
        for (int j = 0; j < 4; ++j) {
            int idx = tid + j * 256;
            int r   = idx >> 4;
            int c4  = (idx & 15) << 2;
            int row = row0 + r;
            float4 v = make_float4(0.f, 0.f, 0.f, 0.f);
            if (row < n) {
                v = *(const float4*)(X + (size_t)row * ldx + kk + c4);
                if (SCALE) {
                    float s = g_dout_is[row];
                    v.x *= s; v.y *= s; v.z *= s; v.w *= s;
                }
            }
            *(float4*)&Xs[r][c4] = v;
            *(float4*)&Ws[r][c4] = *(const float4*)(W + (size_t)(kk + r) * 64 + c4);
        }
        __syncthreads();

        #pragma unroll
        for (int k = 0; k < 64; ++k) {
            float4 wv = *(const float4*)&Ws[k][c0];
            float a0 = Xs[r0 + 0][k];
            float a1 = Xs[r0 + 1][k];
            float a2 = Xs[r0 + 2][k];
            float a3 = Xs[r0 + 3][k];
            acc[0][0] += a0 * wv.x; acc[0][1] += a0 * wv.y; acc[0][2] += a0 * wv.z; acc[0][3] += a0 * wv.w;
            acc[1][0] += a1 * wv.x; acc[1][1] += a1 * wv.y; acc[1][2] += a1 * wv.z; acc[1][3] += a1 * wv.w;
            acc[2][0] += a2 * wv.x; acc[2][1] += a2 * wv.y; acc[2][2] += a2 * wv.z; acc[2][3] += a2 * wv.w;
            acc[3][0] += a3 * wv.x; acc[3][1] += a3 * wv.y; acc[3][2] += a3 * wv.z; acc[3][3] += a3 * wv.w;
        }
        __syncthreads();
    }

    #pragma unroll
    for (int i = 0; i < 4; ++i) {
        int row = row0 + r0 + i;
        if (row < n) {
            float4 o = make_float4(acc[i][0], acc[i][1], acc[i][2], acc[i][3]);
            if (BIAS) {
                float4 bv = *(const float4*)(bias + c0);
                o.x += bv.x; o.y += bv.y; o.z += bv.z; o.w += bv.w;
            }
            *(float4*)(Y + (size_t)row * 64 + c0) = o;
        }
    }
}

__global__ void k_scatter64(const int* __restrict__ src, const int* __restrict__ dst) {
    int t = blockIdx.x * blockDim.x + threadIdx.x;
    int e = t >> 4;
    if (e >= N_EDGES) return;
    int lane = (t & 15) << 2;
    int s = __ldg(src + e);
    int d = __ldg(dst + e);
    float4 v = *(const float4*)(g_y + (size_t)s * HID + lane);
    red_add_v4(g_agg + (size_t)d * HID + lane, v);
}

__global__ void k_scatter256(const int* __restrict__ src, const int* __restrict__ dst) {
    int t = blockIdx.x * blockDim.x + threadIdx.x;
    int e = t >> 6;
    if (e >= N_EDGES) return;
    int lane = (t & 63) << 2;
    int s = __ldg(src + e);
    int d = __ldg(dst + e);
    float4 v = *(const float4*)(g_cat + (size_t)s * CAT_DIM + lane);
    red_add_v4(g_agg256 + (size_t)d * CAT_DIM + lane, v);
}

__global__ void k_epilogue64(const float* __restrict__ bias, int layer) {
    int t = blockIdx.x * blockDim.x + threadIdx.x;
    if (t >= N_NODES * (HID / 4)) return;
    int node = t >> 4;
    int c4   = (t & 15) << 2;
    float s = g_din_is[node];
    float4 v  = *(const float4*)(g_agg + (size_t)node * HID + c4);
    float4 bv = *(const float4*)(bias + c4);
    float4 o;
    o.x = fmaxf(v.x * s + bv.x, 0.f);
    o.y = fmaxf(v.y * s + bv.y, 0.f);
    o.z = fmaxf(v.z * s + bv.z, 0.f);
    o.w = fmaxf(v.w * s + bv.w, 0.f);
    *(float4*)(g_cat + (size_t)node * CAT_DIM + layer * HID + c4) = o;
}

extern "C" void kernel_launch(void* const* d_in, const int* in_sizes, int n_in,
                              void* d_out, int out_size)
{
    const float* feat  = (const float*)d_in[0];
    const int*   src   = (const int*)d_in[1];
    const int*   dst   = (const int*)d_in[2];
    const float* W[4]  = { (const float*)d_in[3], (const float*)d_in[5],
                           (const float*)d_in[7], (const float*)d_in[9] };
    const float* B[4]  = { (const float*)d_in[4], (const float*)d_in[6],
                           (const float*)d_in[8], (const float*)d_in[10] };
    const float* W_mlp = (const float*)d_in[11];
    const float* b_mlp = (const float*)d_in[12];
    float* out = (float*)d_out;

    float *cat_p = nullptr, *agg256_p = nullptr, *y_p = nullptr;
    cudaGetSymbolAddress((void**)&cat_p, g_cat);
    cudaGetSymbolAddress((void**)&agg256_p, g_agg256);
    cudaGetSymbolAddress((void**)&y_p, g_y);

    const int T = 256;
    const int gN      = (N_NODES + T - 1) / T;
    const int gE      = (N_EDGES + T - 1) / T;
    const int gAgg64  = (N_NODES * (HID / 4) + T - 1) / T;
    const int gAgg256 = (N_NODES * (CAT_DIM / 4) + T - 1) / T;
    const int gSc64   = (N_EDGES * 16 + T - 1) / T;
    const int gSc256  = (N_EDGES * 64 + T - 1) / T;
    const int gGemm   = (N_NODES + 63) / 64;

    k_zero_deg<<<gN, T>>>();
    k_deg_count<<<gE, T>>>(src, dst);
    k_deg_fin<<<gN, T>>>();

    k_gemm64<256, true, false><<<gGemm, T>>>(feat, IN_FEATS, W[0], nullptr, y_p, N_NODES);
    k_zero_agg64<<<gAgg64, T>>>();
    k_scatter64<<<gSc64, T>>>(src, dst);
    k_epilogue64<<<gAgg64, T>>>(B[0], 0);

    for (int l = 1; l < 4; ++l) {
        k_gemm64<64, true, false><<<gGemm, T>>>(cat_p + (l - 1) * HID, CAT_DIM,
                                                W[l], nullptr, y_p, N_NODES);
        k_zero_agg64<<<gAgg64, T>>>();
        k_scatter64<<<gSc64, T>>>(src, dst);
        k_epilogue64<<<gAgg64, T>>>(B[l], l);
    }

    k_zero_agg256<<<gAgg256, T>>>();
    k_scatter256<<<gSc256, T>>>(src, dst);
    k_gemm64<256, false, true><<<gGemm, T>>>(agg256_p, CAT_DIM, W_mlp, b_mlp, out, N_NODES);
}

// round 3
// speedup vs baseline: 1.1497x; 1.1497x over previous
#include <cuda_runtime.h>
#include <cuda_bf16.h>
#include <cstdint>

#define N_NODES 50000
#define N_EDGES 800000
#define HID 64
#define CAT_DIM 256

typedef unsigned long long ull;

// ------------------------- device scratch (static, alloc-free) ----------------
__device__ float g_cnt_out[N_NODES];
__device__ float g_cnt_in[N_NODES];
__device__ float g_dout_is[N_NODES];
__device__ float g_din_is[N_NODES];
__device__ float g_y[(size_t)N_NODES * HID];     // per-stage projected features
__device__ float g_agg[(size_t)N_NODES * HID];   // scatter accumulation target
__device__ float g_cat[(size_t)N_NODES * CAT_DIM]; // JK concat buffer [N,256]

// ------------------------- helpers --------------------------------------------
__device__ __forceinline__ void red_add_v4(float* p, float4 v) {
    asm volatile("red.global.add.v4.f32 [%0], {%1, %2, %3, %4};"
                 :: "l"(p), "f"(v.x), "f"(v.y), "f"(v.z), "f"(v.w)
                 : "memory");
}
__device__ __forceinline__ ull pack2(float a) {
    ull r; asm("mov.b64 %0, {%1, %1};" : "=l"(r) : "f"(a)); return r;
}
__device__ __forceinline__ void ffma2(ull& d, ull a, ull b) {
    asm("fma.rn.f32x2 %0, %1, %2, %0;" : "+l"(d) : "l"(a), "l"(b));
}
__device__ __forceinline__ float lo32(ull v) { return __uint_as_float((unsigned)v); }
__device__ __forceinline__ float hi32(ull v) { return __uint_as_float((unsigned)(v >> 32)); }

// ------------------------- small kernels ---------------------------------------
__global__ void k_zero_deg() {
    int i = blockIdx.x * blockDim.x + threadIdx.x;
    if (i < N_NODES) { g_cnt_out[i] = 0.f; g_cnt_in[i] = 0.f; }
}

__global__ void k_zero_agg64() {
    int i = blockIdx.x * blockDim.x + threadIdx.x;
    if (i < N_NODES * (HID / 4)) ((float4*)g_agg)[i] = make_float4(0.f, 0.f, 0.f, 0.f);
}

__global__ void k_deg_count(const int* __restrict__ src, const int* __restrict__ dst) {
    int e = blockIdx.x * blockDim.x + threadIdx.x;
    if (e < N_EDGES) {
        atomicAdd(&g_cnt_out[src[e]], 1.f);
        atomicAdd(&g_cnt_in[dst[e]], 1.f);
    }
}

__global__ void k_deg_fin() {
    int i = blockIdx.x * blockDim.x + threadIdx.x;
    if (i < N_NODES) {
        g_dout_is[i] = rsqrtf(fmaxf(g_cnt_out[i], 1.f));
        g_din_is[i]  = rsqrtf(fmaxf(g_cnt_in[i], 1.f));
    }
}

// ------------------------- FFMA2 GEMM: Y[n,64] = (diag(s?) X[n,K]) @ W[K,64] ----
// Tile: 128 rows x 64 cols, BK=32, 256 threads, 8 rows x 4 cols per thread.
// X tile stored k-major (transposed) so adjacent M-rows form natural f32x2 pairs;
// W tile stored duplicated (w,w) so broadcast operands are natural 64-bit loads.
template<int K, bool SCALE>
__global__ __launch_bounds__(256)
void k_gemm(const float* __restrict__ X, int ldx,
            const float* __restrict__ W,
            float* __restrict__ Y, int n)
{
    __shared__ float Xs[32][132];   // [k][row], padded row (132 mod 4 == 0 for LDS.128)
    __shared__ ull   Wd[32][64];    // [k][col] duplicated pairs

    const int tid  = threadIdx.x;
    const int row0 = blockIdx.x * 128;
    const int r0   = (tid >> 4) * 8;   // 8 rows -> 4 row-pairs
    const int c0   = (tid & 15) * 4;   // 4 cols

    ull acc[4][4];
    #pragma unroll
    for (int p = 0; p < 4; ++p)
        #pragma unroll
        for (int j = 0; j < 4; ++j) acc[p][j] = 0ull;

    for (int kk = 0; kk < K; kk += 32) {
        // load X tile, transpose into Xs[k][row]
        #pragma unroll
        for (int j = 0; j < 4; ++j) {
            int idx = tid + j * 256;       // 0..1023
            int r   = idx >> 3;            // row 0..127
            int c4  = (idx & 7) * 4;       // k offset 0..28
            int row = row0 + r;
            float4 v = make_float4(0.f, 0.f, 0.f, 0.f);
            if (row < n) {
                v = *(const float4*)(X + (size_t)row * ldx + kk + c4);
                if (SCALE) {
                    float s = __ldg(&g_dout_is[row]);
                    v.x *= s; v.y *= s; v.z *= s; v.w *= s;
                }
            }
            Xs[c4 + 0][r] = v.x;
            Xs[c4 + 1][r] = v.y;
            Xs[c4 + 2][r] = v.z;
            Xs[c4 + 3][r] = v.w;
        }
        // load W tile, duplicate each scalar into (w,w)
        #pragma unroll
        for (int j = 0; j < 8; ++j) {
            int idx = tid + j * 256;       // 0..2047
            int k   = idx >> 6;            // 0..31
            int c   = idx & 63;            // 0..63
            Wd[k][c] = pack2(W[(size_t)(kk + k) * 64 + c]);
        }
        __syncthreads();

        #pragma unroll
        for (int k = 0; k < 32; ++k) {
            double2 xa = *(const double2*)&Xs[k][r0];       // row-pairs 0,1
            double2 xb = *(const double2*)&Xs[k][r0 + 4];   // row-pairs 2,3
            double2 wA = *(const double2*)&Wd[k][c0];       // cols c0, c0+1
            double2 wB = *(const double2*)&Wd[k][c0 + 2];   // cols c0+2, c0+3
            ull a0 = __double_as_longlong(xa.x);
            ull a1 = __double_as_longlong(xa.y);
            ull a2 = __double_as_longlong(xb.x);
            ull a3 = __double_as_longlong(xb.y);
            ull w0 = __double_as_longlong(wA.x);
            ull w1 = __double_as_longlong(wA.y);
            ull w2 = __double_as_longlong(wB.x);
            ull w3 = __double_as_longlong(wB.y);
            ffma2(acc[0][0], a0, w0); ffma2(acc[0][1], a0, w1); ffma2(acc[0][2], a0, w2); ffma2(acc[0][3], a0, w3);
            ffma2(acc[1][0], a1, w0); ffma2(acc[1][1], a1, w1); ffma2(acc[1][2], a1, w2); ffma2(acc[1][3], a1, w3);
            ffma2(acc[2][0], a2, w0); ffma2(acc[2][1], a2, w1); ffma2(acc[2][2], a2, w2); ffma2(acc[2][3], a2, w3);
            ffma2(acc[3][0], a3, w0); ffma2(acc[3][1], a3, w1); ffma2(acc[3][2], a3, w2); ffma2(acc[3][3], a3, w3);
        }
        __syncthreads();
    }

    #pragma unroll
    for (int p = 0; p < 4; ++p) {
        int rowA = row0 + r0 + 2 * p;
        if (rowA < n) {
            float4 o = make_float4(lo32(acc[p][0]), lo32(acc[p][1]), lo32(acc[p][2]), lo32(acc[p][3]));
            *(float4*)(Y + (size_t)rowA * 64 + c0) = o;
        }
        if (rowA + 1 < n) {
            float4 o = make_float4(hi32(acc[p][0]), hi32(acc[p][1]), hi32(acc[p][2]), hi32(acc[p][3]));
            *(float4*)(Y + (size_t)(rowA + 1) * 64 + c0) = o;
        }
    }
}

// ------------------------- edge scatter: g_agg[dst] += g_y[src], 64 wide -------
__global__ void k_scatter64(const int* __restrict__ src, const int* __restrict__ dst) {
    int t = blockIdx.x * blockDim.x + threadIdx.x;   // E*16 threads
    int e = t >> 4;
    if (e >= N_EDGES) return;
    int lane = (t & 15) << 2;
    int s = __ldg(src + e);
    int d = __ldg(dst + e);
    float4 v = *(const float4*)(g_y + (size_t)s * HID + lane);
    red_add_v4(g_agg + (size_t)d * HID + lane, v);
}

// ------------------------- layer epilogue: relu(agg*din+b) -> cat, reset agg ---
__global__ void k_epilogue64(const float* __restrict__ bias, int layer) {
    int t = blockIdx.x * blockDim.x + threadIdx.x;
    if (t >= N_NODES * (HID / 4)) return;
    int node = t >> 4;
    int c4   = (t & 15) << 2;
    float s = g_din_is[node];
    float4 v  = *(const float4*)(g_agg + (size_t)node * HID + c4);
    float4 bv = *(const float4*)(bias + c4);
    float4 o;
    o.x = fmaxf(fmaf(v.x, s, bv.x), 0.f);
    o.y = fmaxf(fmaf(v.y, s, bv.y), 0.f);
    o.z = fmaxf(fmaf(v.z, s, bv.z), 0.f);
    o.w = fmaxf(fmaf(v.w, s, bv.w), 0.f);
    *(float4*)(g_cat + (size_t)node * CAT_DIM + layer * HID + c4) = o;
    // reset for next scatter (fused zeroing)
    *(float4*)(g_agg + (size_t)node * HID + c4) = make_float4(0.f, 0.f, 0.f, 0.f);
}

// ------------------------- final epilogue: out = agg + b_mlp -------------------
__global__ void k_final_epi(const float* __restrict__ bias, float* __restrict__ out) {
    int t = blockIdx.x * blockDim.x + threadIdx.x;
    if (t >= N_NODES * (HID / 4)) return;
    int node = t >> 4;
    int c4   = (t & 15) << 2;
    float4 v  = *(const float4*)(g_agg + (size_t)node * HID + c4);
    float4 bv = *(const float4*)(bias + c4);
    float4 o = make_float4(v.x + bv.x, v.y + bv.y, v.z + bv.z, v.w + bv.w);
    *(float4*)(out + (size_t)node * HID + c4) = o;
}

// ------------------------- launch ----------------------------------------------
extern "C" void kernel_launch(void* const* d_in, const int* in_sizes, int n_in,
                              void* d_out, int out_size)
{
    const float* feat  = (const float*)d_in[0];
    const int*   src   = (const int*)d_in[1];
    const int*   dst   = (const int*)d_in[2];
    const float* W[4]  = { (const float*)d_in[3], (const float*)d_in[5],
                           (const float*)d_in[7], (const float*)d_in[9] };
    const float* B[4]  = { (const float*)d_in[4], (const float*)d_in[6],
                           (const float*)d_in[8], (const float*)d_in[10] };
    const float* W_mlp = (const float*)d_in[11];
    const float* b_mlp = (const float*)d_in[12];
    float* out = (float*)d_out;

    float *cat_p = nullptr, *y_p = nullptr;
    cudaGetSymbolAddress((void**)&cat_p, g_cat);
    cudaGetSymbolAddress((void**)&y_p, g_y);

    const int T = 256;
    const int gN     = (N_NODES + T - 1) / T;
    const int gE     = (N_EDGES + T - 1) / T;
    const int gAgg64 = (N_NODES * (HID / 4) + T - 1) / T;
    const int gSc64  = (N_EDGES * 16 + T - 1) / T;
    const int gGemm  = (N_NODES + 127) / 128;

    // degrees + initial agg zero
    k_zero_deg<<<gN, T>>>();
    k_deg_count<<<gE, T>>>(src, dst);
    k_deg_fin<<<gN, T>>>();
    k_zero_agg64<<<gAgg64, T>>>();

    // layer 0: K = 256, input = feat
    k_gemm<256, true><<<gGemm, T>>>(feat, 256, W[0], y_p, N_NODES);
    k_scatter64<<<gSc64, T>>>(src, dst);
    k_epilogue64<<<gAgg64, T>>>(B[0], 0);

    // layers 1..3: K = 64, input = cat column block of previous layer (ld = 256)
    for (int l = 1; l < 4; ++l) {
        k_gemm<64, true><<<gGemm, T>>>(cat_p + (l - 1) * HID, CAT_DIM, W[l], y_p, N_NODES);
        k_scatter64<<<gSc64, T>>>(src, dst);
        k_epilogue64<<<gAgg64, T>>>(B[l], l);
    }

    // final stage, reordered by linearity:
    //   out = segment_sum(cat[src]) @ W_mlp + b  ==  segment_sum((cat @ W_mlp)[src]) + b
    k_gemm<256, false><<<gGemm, T>>>(cat_p, CAT_DIM, W_mlp, y_p, N_NODES);
    k_scatter64<<<gSc64, T>>>(src, dst);
    k_final_epi<<<gAgg64, T>>>(b_mlp, out);
}